// round 4
// baseline (speedup 1.0000x reference)
#include <cuda_runtime.h>
#include <math.h>
#include <stdint.h>

// ---------------- capacities (match problem shapes) ----------------
#define NMAX 100096      // 100000 nodes, padded
#define EMAX 1600000
#define BMAX 16384
#define FDIM 128
#define HDIM 128

// ---------------- device scratch (no allocs allowed) ----------------
__device__ float d_mean0[(size_t)NMAX * FDIM];   // layer0 neighbor mean, later unused
__device__ float d_h   [(size_t)NMAX * HDIM];    // layer0 output
__device__ float d_aggU[(size_t)BMAX * HDIM];    // layer1 neighbor mean (user rows only)
__device__ float d_ue  [(size_t)BMAX * HDIM];    // clipped user embeddings
__device__ float d_gate[(size_t)BMAX * 512];     // LSTM gates
__device__ float d_lstm[(size_t)BMAX * HDIM];    // LSTM output
__device__ float d_z0  [(size_t)BMAX * HDIM];
__device__ float d_z1  [(size_t)BMAX * 64];
__device__ int   d_count [NMAX];
__device__ int   d_rowptr[NMAX];
__device__ int   d_cursor[NMAX];
__device__ int   d_srcs  [EMAX];
__device__ int   d_bsum  [1024];

__device__ __forceinline__ float clamp10(float v) {
    return fminf(10.0f, fmaxf(-10.0f, v));
}

// ---------------- CSR build ----------------
__global__ void k_zero(int n) {
    int i = blockIdx.x * blockDim.x + threadIdx.x;
    if (i < n) { d_count[i] = 0; d_cursor[i] = 0; }
}

__global__ void k_count(const int* __restrict__ dst, int E) {
    int e = blockIdx.x * blockDim.x + threadIdx.x;
    if (e < E) atomicAdd(&d_count[dst[e]], 1);
}

__global__ void k_scan1(int n) {
    __shared__ int sh[1024];
    int i = blockIdx.x * 1024 + threadIdx.x;
    int v = (i < n) ? d_count[i] : 0;
    sh[threadIdx.x] = v;
    __syncthreads();
    for (int off = 1; off < 1024; off <<= 1) {
        int t = (threadIdx.x >= off) ? sh[threadIdx.x - off] : 0;
        __syncthreads();
        sh[threadIdx.x] += t;
        __syncthreads();
    }
    if (i < n) d_rowptr[i] = sh[threadIdx.x] - v;   // exclusive
    if (threadIdx.x == 1023) d_bsum[blockIdx.x] = sh[1023];
}

__global__ void k_scan2(int nb) {
    __shared__ int sh[1024];
    int v = (threadIdx.x < nb) ? d_bsum[threadIdx.x] : 0;
    sh[threadIdx.x] = v;
    __syncthreads();
    for (int off = 1; off < 1024; off <<= 1) {
        int t = (threadIdx.x >= off) ? sh[threadIdx.x - off] : 0;
        __syncthreads();
        sh[threadIdx.x] += t;
        __syncthreads();
    }
    if (threadIdx.x < nb) d_bsum[threadIdx.x] = sh[threadIdx.x] - v;  // exclusive
}

__global__ void k_scan3(int n) {
    int i = blockIdx.x * blockDim.x + threadIdx.x;
    if (i < n) d_rowptr[i] += d_bsum[i >> 10];
}

__global__ void k_scatter(const int* __restrict__ src, const int* __restrict__ dst, int E) {
    int e = blockIdx.x * blockDim.x + threadIdx.x;
    if (e < E) {
        int d = dst[e];
        int pos = atomicAdd(&d_cursor[d], 1);
        d_srcs[d_rowptr[d] + pos] = src[e];
    }
}

// ---------------- mean aggregation: one warp per output row ----------------
// out[w] = mean_{s in N(node)} X[s], node = gath ? gath[w] : w
__global__ void k_agg(const float* __restrict__ X, const int* __restrict__ gath,
                      float* __restrict__ out, int nrows) {
    int w = (blockIdx.x * blockDim.x + threadIdx.x) >> 5;
    int lane = threadIdx.x & 31;
    if (w >= nrows) return;
    int node = gath ? gath[w] : w;
    int start = d_rowptr[node];
    int cnt   = d_count[node];
    float4 acc = make_float4(0.f, 0.f, 0.f, 0.f);
    for (int j = 0; j < cnt; j++) {
        int s = d_srcs[start + j];
        float4 v = *reinterpret_cast<const float4*>(X + (size_t)s * 128 + (lane << 2));
        acc.x += v.x; acc.y += v.y; acc.z += v.z; acc.w += v.w;
    }
    float inv = 1.0f / fmaxf((float)cnt, 1.0f);
    acc.x *= inv; acc.y *= inv; acc.z *= inv; acc.w *= inv;
    *reinterpret_cast<float4*>(out + (size_t)w * 128 + (lane << 2)) = acc;
}

// ---------------- generic fused SGEMM ----------------
// C[M, Nout] = act( [A0 | A1(gathered,clipped)] @ [W0 | W1]^T + bias1 + bias2 + roleW[:, roleOff + roles[row]] )
// A0: [M, K0] stride K0.  A1 rows: g1 ? g1[row] : row, stride K1.
// W0: [Nout, K0] stride ldw0 (k < K0).  W1: [Nout, K1] stride ldw1 (k >= K0).
// act: 0 none, 1 relu, 2 clip(+-10)
__global__ __launch_bounds__(256, 2)
void k_sgemm(const float* __restrict__ A0, const float* __restrict__ A1,
             const int* __restrict__ g1, int clip1, int K0, int K1,
             const float* __restrict__ W0, int ldw0,
             const float* __restrict__ W1, int ldw1,
             const float* __restrict__ bias1, const float* __restrict__ bias2,
             const float* __restrict__ roleW, int roleLd, int roleOff,
             const int* __restrict__ roles,
             float* __restrict__ C, int ldc, int M, int Nout, int act) {
    __shared__ float As[16][128];
    __shared__ float Bs[16][128];
    const int tid = threadIdx.x;
    const int tx = tid & 15, ty = tid >> 4;
    const int rowBase = blockIdx.y * 128;
    const int colBase = blockIdx.x * 128;
    const int K = K0 + K1;

    float acc[8][8];
#pragma unroll
    for (int i = 0; i < 8; i++)
#pragma unroll
        for (int j = 0; j < 8; j++) acc[i][j] = 0.f;

    for (int kt = 0; kt < K; kt += 16) {
        // load A tile (128 rows x 16 k) as float4 per thread x2, transpose into As[k][m]
#pragma unroll
        for (int it = 0; it < 2; it++) {
            int idx = tid + it * 256;       // 0..511
            int m = idx >> 2;               // 0..127
            int kq = (idx & 3) << 2;        // 0,4,8,12
            int row = rowBase + m;
            float4 v = make_float4(0.f, 0.f, 0.f, 0.f);
            if (row < M) {
                int kg = kt + kq;
                if (kg < K0) {
                    v = *reinterpret_cast<const float4*>(A0 + (size_t)row * K0 + kg);
                } else {
                    int r1 = g1 ? g1[row] : row;
                    v = *reinterpret_cast<const float4*>(A1 + (size_t)r1 * K1 + (kg - K0));
                    if (clip1) {
                        v.x = clamp10(v.x); v.y = clamp10(v.y);
                        v.z = clamp10(v.z); v.w = clamp10(v.w);
                    }
                }
            }
            As[kq + 0][m] = v.x; As[kq + 1][m] = v.y;
            As[kq + 2][m] = v.z; As[kq + 3][m] = v.w;
        }
        // load W tile (128 n x 16 k), scalar loads (w_ih stride 261 is not 16B aligned)
#pragma unroll
        for (int it = 0; it < 8; it++) {
            int idx = tid + it * 256;       // 0..2047
            int n = idx >> 4;               // 0..127
            int kk = idx & 15;
            int ng = colBase + n;
            float wv = 0.f;
            if (ng < Nout) {
                int kg = kt + kk;
                wv = (kg < K0) ? W0[(size_t)ng * ldw0 + kg]
                               : W1[(size_t)ng * ldw1 + (kg - K0)];
            }
            Bs[kk][n] = wv;
        }
        __syncthreads();
#pragma unroll
        for (int kk = 0; kk < 16; kk++) {
            float a[8], b[8];
#pragma unroll
            for (int i = 0; i < 8; i++) a[i] = As[kk][ty * 8 + i];
#pragma unroll
            for (int j = 0; j < 8; j++) b[j] = Bs[kk][tx * 8 + j];
#pragma unroll
            for (int i = 0; i < 8; i++)
#pragma unroll
                for (int j = 0; j < 8; j++) acc[i][j] += a[i] * b[j];
        }
        __syncthreads();
    }

    // epilogue
#pragma unroll
    for (int i = 0; i < 8; i++) {
        int row = rowBase + ty * 8 + i;
        if (row >= M) continue;
        int rl = roleW ? roles[row] : 0;
#pragma unroll
        for (int j = 0; j < 8; j++) {
            int n = colBase + tx * 8 + j;
            if (n >= Nout) continue;
            float v = acc[i][j];
            if (bias1) v += bias1[n];
            if (bias2) v += bias2[n];
            if (roleW) v += roleW[(size_t)n * roleLd + roleOff + rl];
            if (act == 1) v = fmaxf(v, 0.f);
            else if (act == 2) v = clamp10(v);
            C[(size_t)row * ldc + n] = v;
        }
    }
}

// ---------------- LSTM pointwise (h0=c0=0: c = sig(i)*tanh(g); out = clip(sig(o)*tanh(c))) ----------------
__global__ void k_lstm(int B) {
    int idx = blockIdx.x * blockDim.x + threadIdx.x;
    if (idx >= B * 128) return;
    int b = idx >> 7, j = idx & 127;
    const float* g = d_gate + (size_t)b * 512;
    float i_ = g[j];           // gate i
    float gg = g[256 + j];     // gate g
    float o_ = g[384 + j];     // gate o
    float si = 1.0f / (1.0f + expf(-i_));
    float so = 1.0f / (1.0f + expf(-o_));
    float c = si * tanhf(gg);
    d_lstm[idx] = clamp10(so * tanhf(c));
}

// ---------------- final tiny layer: out[B,5] = z1[B,64] @ wc2[5,64]^T + bc2 ----------------
__global__ void k_out(const float* __restrict__ wc2, const float* __restrict__ bc2,
                      float* __restrict__ out, int B) {
    __shared__ float w[320];
    __shared__ float bb[5];
    int tid = threadIdx.x;
    if (tid < 320) w[tid] = wc2[tid];
    if (tid < 5)   bb[tid] = bc2[tid];
    __syncthreads();
    int b = blockIdx.x * blockDim.x + tid;
    if (b >= B) return;
    const float* z = d_z1 + (size_t)b * 64;
    float a0 = bb[0], a1 = bb[1], a2 = bb[2], a3 = bb[3], a4 = bb[4];
#pragma unroll
    for (int k = 0; k < 64; k++) {
        float zv = z[k];
        a0 += zv * w[k];
        a1 += zv * w[64 + k];
        a2 += zv * w[128 + k];
        a3 += zv * w[192 + k];
        a4 += zv * w[256 + k];
    }
    float* o = out + (size_t)b * 5;
    o[0] = a0; o[1] = a1; o[2] = a2; o[3] = a3; o[4] = a4;
}

// ---------------- launch ----------------
extern "C" void kernel_launch(void* const* d_in, const int* in_sizes, int n_in,
                              void* d_out, int out_size) {
    const float* x     = (const float*)d_in[0];
    const int*   edge  = (const int*)  d_in[1];
    const int*   uid   = (const int*)  d_in[2];
    const int*   roles = (const int*)  d_in[3];
    const float* w_l0  = (const float*)d_in[4];
    const float* b_l0  = (const float*)d_in[5];
    const float* w_r0  = (const float*)d_in[6];
    const float* w_l1  = (const float*)d_in[7];
    const float* b_l1  = (const float*)d_in[8];
    const float* w_r1  = (const float*)d_in[9];
    const float* w_ih  = (const float*)d_in[10];
    /* w_hh = d_in[11] unused: h0 = 0 */
    const float* b_ih  = (const float*)d_in[12];
    const float* b_hh  = (const float*)d_in[13];
    const float* wc0   = (const float*)d_in[14];
    const float* bc0   = (const float*)d_in[15];
    const float* wc1   = (const float*)d_in[16];
    const float* bc1   = (const float*)d_in[17];
    const float* wc2   = (const float*)d_in[18];
    const float* bc2   = (const float*)d_in[19];
    float* out = (float*)d_out;

    const int N = in_sizes[0] / FDIM;
    const int E = in_sizes[1] / 2;
    const int B = in_sizes[2];
    const int* src = edge;
    const int* dst = edge + E;

    float *mean0, *hbuf, *aggU, *ue, *gate, *lstm, *z0, *z1;
    cudaGetSymbolAddress((void**)&mean0, d_mean0);
    cudaGetSymbolAddress((void**)&hbuf,  d_h);
    cudaGetSymbolAddress((void**)&aggU,  d_aggU);
    cudaGetSymbolAddress((void**)&ue,    d_ue);
    cudaGetSymbolAddress((void**)&gate,  d_gate);
    cudaGetSymbolAddress((void**)&lstm,  d_lstm);
    cudaGetSymbolAddress((void**)&z0,    d_z0);
    cudaGetSymbolAddress((void**)&z1,    d_z1);

    // --- CSR build (shared by both SAGE layers) ---
    k_zero<<<(N + 255) / 256, 256>>>(N);
    k_count<<<(E + 255) / 256, 256>>>(dst, E);
    int nb = (N + 1023) / 1024;
    k_scan1<<<nb, 1024>>>(N);
    k_scan2<<<1, 1024>>>(nb);
    k_scan3<<<(N + 255) / 256, 256>>>(N);
    k_scatter<<<(E + 255) / 256, 256>>>(src, dst, E);

    // --- layer 0: mean over neighbors of x, then h = relu([mean|x] @ [w_l0|w_r0]^T + b_l0) ---
    k_agg<<<(N + 7) / 8, 256>>>(x, nullptr, mean0, N);
    {
        dim3 g((HDIM + 127) / 128, (N + 127) / 128);
        k_sgemm<<<g, 256>>>(mean0, x, nullptr, 0, 128, 128,
                            w_l0, 128, w_r0, 128,
                            b_l0, nullptr,
                            nullptr, 0, 0, nullptr,
                            hbuf, 128, N, HDIM, /*relu*/1);
    }

    // --- layer 1 restricted to user rows: aggU[b] = mean over N(uid[b]) of h ---
    k_agg<<<(B + 7) / 8, 256>>>(hbuf, uid, aggU, B);
    {   // ue = clip([aggU | h[uid]] @ [w_l1|w_r1]^T + b_l1)
        dim3 g(1, (B + 127) / 128);
        k_sgemm<<<g, 256>>>(aggU, hbuf, uid, 0, 128, 128,
                            w_l1, 128, w_r1, 128,
                            b_l1, nullptr,
                            nullptr, 0, 0, nullptr,
                            ue, 128, B, HDIM, /*clip*/2);
    }

    // --- gates = [ue | clip(x[uid])] @ w_ih[:, :256]^T + w_ih[:, 256+role] + b_ih + b_hh ---
    {
        dim3 g(4, (B + 127) / 128);
        k_sgemm<<<g, 256>>>(ue, x, uid, /*clip uf*/1, 128, 128,
                            w_ih, 261, w_ih + 128, 261,
                            b_ih, b_hh,
                            w_ih, 261, 256, roles,
                            gate, 512, B, 512, /*none*/0);
    }
    k_lstm<<<(B * 128 + 255) / 256, 256>>>(B);

    // --- classifier head ---
    {   // z0 = relu([ue | lstm] @ wc0^T + bc0)
        dim3 g(1, (B + 127) / 128);
        k_sgemm<<<g, 256>>>(ue, lstm, nullptr, 0, 128, 128,
                            wc0, 256, wc0 + 128, 256,
                            bc0, nullptr,
                            nullptr, 0, 0, nullptr,
                            z0, 128, B, 128, 1);
    }
    {   // z1 = relu(z0 @ wc1^T + bc1)   (Nout = 64)
        dim3 g(1, (B + 127) / 128);
        k_sgemm<<<g, 256>>>(z0, nullptr, nullptr, 0, 128, 0,
                            wc1, 128, nullptr, 0,
                            bc1, nullptr,
                            nullptr, 0, 0, nullptr,
                            z1, 64, B, 64, 1);
    }
    k_out<<<(B + 511) / 512, 512>>>(wc2, bc2, out, B);
}